// round 3
// baseline (speedup 1.0000x reference)
#include <cuda_runtime.h>
#include <math.h>

// ---------------- problem constants ----------------
#define TB   8        // batch
#define LT   512      // tgt len
#define LS   512      // src len
#define DM   512      // d_model
#define NH   8        // heads
#define DK   64
#define DV   64
#define DI   2048     // ffn inner
#define NL   6        // layers
#define TOK  (TB*LT)  // 4096 tokens
#define HB   (NH*TB)  // 64 attention batches

#define EPSLN 1e-5f
// 1/sqrt(d_model) = 1/sqrt(512)
#define ATT_SCALE 0.044194173824159216f

// out layout: [x (TOK*DM)] [slf_attns (NL*HB*LT*LT)] [enc_attns (NL*HB*LT*LT)]
#define X_SIZE   ((size_t)TOK*DM)                    // 2,097,152
#define ATT_L    ((size_t)HB*LT*LT)                  // 16,777,216 per layer
#define SLF_SIZE ((size_t)NL*ATT_L)

// ---------------- scratch (no allocations allowed) ----------------
__device__ float g_x  [TOK*DM];
__device__ float g_tmp[TOK*DM];
__device__ float g_q  [TOK*DM];
__device__ float g_k  [TOK*DM];
__device__ float g_v  [TOK*DM];
__device__ float g_ao [TOK*DM];
__device__ float g_ffn[TOK*DI];
// 6 transposed qkv weight sets: slf q/k/v, enc q/k/v; each [NL, DM, NH*DK]
#define WSTR ((size_t)NL*DM*NH*DK)
__device__ float g_wT[6*NL*DM*NH*DK];

// ---------------- embedding ----------------
__global__ void embed_kernel(const int* __restrict__ seq, const int* __restrict__ pos,
                             const float* __restrict__ emb, const float* __restrict__ pemb,
                             float* __restrict__ x)
{
    int i = blockIdx.x * 256 + threadIdx.x;   // over TOK*DM
    int t = i / DM, d = i % DM;
    x[i] = emb[(size_t)seq[t]*DM + d] + pemb[(size_t)pos[t]*DM + d];
}

// ---------------- qkv weight transpose: [NL,NH,DM,DK] -> [NL,DM,NH*DK] ----------------
__global__ void transw_kernel(const float* __restrict__ w, float* __restrict__ wt)
{
    int i = blockIdx.x * 256 + threadIdx.x;   // NL*NH*DM*DK elements
    int e = i % DK;
    int d = (i / DK) % DM;
    int h = (i / (DK*DM)) % NH;
    int l = i / (DK*DM*NH);
    wt[((size_t)l*DM + d)*(NH*DK) + h*DK + e] = w[i];
}

// ---------------- generic row-major GEMM: C[M,N] = A[M,K] @ B[K,N] ----------------
// 64x64 tile, BK=16, 256 threads, 4x4 micro-tile. All dims multiples of tiles.
template<bool BIAS, bool RES, bool RELU>
__global__ void __launch_bounds__(256) gemm_kernel(
    const float* __restrict__ A, const float* __restrict__ Bm,
    const float* __restrict__ bias, const float* __restrict__ res,
    float* __restrict__ C, int M, int N, int K)
{
    __shared__ float As[16][64];   // transposed: As[k][m]
    __shared__ float Bs[16][64];   // Bs[k][n]
    int tid = threadIdx.x;
    int tx = tid & 15, ty = tid >> 4;
    int bm = blockIdx.x * 64, bn = blockIdx.y * 64;

    int am = tid >> 2;            // 0..63
    int ak = (tid & 3) * 4;       // 0,4,8,12
    int bk = tid >> 4;            // 0..15
    int bn4 = (tid & 15) * 4;     // 0..60

    const float* Aptr = A + (size_t)(bm + am) * K + ak;
    const float* Bptr = Bm + (size_t)bk * N + bn + bn4;

    float acc[4][4] = {};
    for (int kt = 0; kt < K; kt += 16) {
        float4 a = *(const float4*)(Aptr + kt);
        float4 b = *(const float4*)(Bptr + (size_t)kt * N);
        As[ak+0][am] = a.x; As[ak+1][am] = a.y; As[ak+2][am] = a.z; As[ak+3][am] = a.w;
        *(float4*)&Bs[bk][bn4] = b;
        __syncthreads();
#pragma unroll
        for (int k = 0; k < 16; k++) {
            float4 av = *(const float4*)&As[k][ty*4];
            float4 bv = *(const float4*)&Bs[k][tx*4];
            float aa[4] = {av.x, av.y, av.z, av.w};
            float bb[4] = {bv.x, bv.y, bv.z, bv.w};
#pragma unroll
            for (int i = 0; i < 4; i++)
#pragma unroll
                for (int j = 0; j < 4; j++)
                    acc[i][j] += aa[i] * bb[j];
        }
        __syncthreads();
    }
#pragma unroll
    for (int i = 0; i < 4; i++) {
        int m = bm + ty*4 + i;
        int n = bn + tx*4;
        float4 cv = make_float4(acc[i][0], acc[i][1], acc[i][2], acc[i][3]);
        if (BIAS) {
            float4 bv = *(const float4*)(bias + n);
            cv.x += bv.x; cv.y += bv.y; cv.z += bv.z; cv.w += bv.w;
        }
        if (RES) {
            float4 rv = *(const float4*)(res + (size_t)m*N + n);
            cv.x += rv.x; cv.y += rv.y; cv.z += rv.z; cv.w += rv.w;
        }
        if (RELU) {
            cv.x = fmaxf(cv.x, 0.f); cv.y = fmaxf(cv.y, 0.f);
            cv.z = fmaxf(cv.z, 0.f); cv.w = fmaxf(cv.w, 0.f);
        }
        *(float4*)(C + (size_t)m*N + n) = cv;
    }
}

// ---------------- batched attention scores: S[z,q,s] = scale * Q[z,q,:]·K[z,s,:] ----------------
// Q/K stored as [b*LT + t, NH*DK] row-major; head offset h*DK. grid (LT/64, LT/64, HB)
__global__ void __launch_bounds__(256) attn_score_kernel(
    const float* __restrict__ Q, const float* __restrict__ Kk, float* __restrict__ out)
{
    __shared__ float Qs[64][68];   // [e][q]
    __shared__ float Ks[64][68];   // [e][s]
    int z = blockIdx.z;
    int h = z >> 3, b = z & 7;
    const float* Qb = Q + ((size_t)b*LT)*DM + h*DK;
    const float* Kb = Kk + ((size_t)b*LT)*DM + h*DK;
    int q0 = blockIdx.x * 64, s0 = blockIdx.y * 64;
    int tid = threadIdx.x;
    int lr = tid >> 4;            // 0..15
    int c4 = (tid & 15) * 4;      // e chunk
#pragma unroll
    for (int rr = 0; rr < 4; rr++) {
        int row = lr + rr*16;
        float4 qa = *(const float4*)(Qb + (size_t)(q0+row)*DM + c4);
        float4 ka = *(const float4*)(Kb + (size_t)(s0+row)*DM + c4);
        Qs[c4+0][row]=qa.x; Qs[c4+1][row]=qa.y; Qs[c4+2][row]=qa.z; Qs[c4+3][row]=qa.w;
        Ks[c4+0][row]=ka.x; Ks[c4+1][row]=ka.y; Ks[c4+2][row]=ka.z; Ks[c4+3][row]=ka.w;
    }
    __syncthreads();
    int tx = tid & 15, ty = tid >> 4;
    float acc[4][4] = {};
#pragma unroll 8
    for (int e = 0; e < 64; e++) {
        float4 qv = *(const float4*)&Qs[e][ty*4];
        float4 kv = *(const float4*)&Ks[e][tx*4];
        float aa[4] = {qv.x,qv.y,qv.z,qv.w};
        float bb[4] = {kv.x,kv.y,kv.z,kv.w};
#pragma unroll
        for (int i = 0; i < 4; i++)
#pragma unroll
            for (int j = 0; j < 4; j++)
                acc[i][j] += aa[i]*bb[j];
    }
    float* Cb = out + (size_t)z*LT*LT;
#pragma unroll
    for (int i = 0; i < 4; i++) {
        float4 cv = make_float4(acc[i][0]*ATT_SCALE, acc[i][1]*ATT_SCALE,
                                acc[i][2]*ATT_SCALE, acc[i][3]*ATT_SCALE);
        *(float4*)(Cb + (size_t)(q0+ty*4+i)*LT + s0 + tx*4) = cv;
    }
}

// ---------------- masked softmax over rows of 512, in place ----------------
// grid (LT, HB), 128 threads; SELF: causal + tgt pad; else: src pad.
template<bool SELF>
__global__ void softmax_kernel(float* __restrict__ attn, const int* __restrict__ seq)
{
    __shared__ float sh[4];
    int q = blockIdx.x;
    int z = blockIdx.y;
    int b = z & 7;
    float* row = attn + ((size_t)z*LT + q)*LT;
    int tid = threadIdx.x;
    float v[4];
    float mx = -INFINITY;
#pragma unroll
    for (int i = 0; i < 4; i++) {
        int s = tid + i*128;
        bool m;
        if (SELF) m = (s > q) || (seq[b*LT + s] == 0);
        else      m = (seq[b*LS + s] == 0);
        float val = m ? -INFINITY : row[s];
        v[i] = val;
        mx = fmaxf(mx, val);
    }
#pragma unroll
    for (int o = 16; o > 0; o >>= 1) mx = fmaxf(mx, __shfl_xor_sync(0xffffffffu, mx, o));
    if ((tid & 31) == 0) sh[tid >> 5] = mx;
    __syncthreads();
    mx = fmaxf(fmaxf(sh[0], sh[1]), fmaxf(sh[2], sh[3]));
    float sum = 0.f;
#pragma unroll
    for (int i = 0; i < 4; i++) { v[i] = __expf(v[i] - mx); sum += v[i]; }
#pragma unroll
    for (int o = 16; o > 0; o >>= 1) sum += __shfl_xor_sync(0xffffffffu, sum, o);
    __syncthreads();
    if ((tid & 31) == 0) sh[tid >> 5] = sum;
    __syncthreads();
    sum = sh[0] + sh[1] + sh[2] + sh[3];
    float inv = 1.f / sum;
#pragma unroll
    for (int i = 0; i < 4; i++) row[tid + i*128] = v[i] * inv;
}

// ---------------- batched P@V: C[b,q, h*DV+e] = sum_s P[z,q,s] V[b,s, h*DV+e] ----------------
// grid (LT/64, 1, HB)
__global__ void __launch_bounds__(256) attn_pv_kernel(
    const float* __restrict__ P, const float* __restrict__ V, float* __restrict__ Cout)
{
    __shared__ float Ps[32][68];   // [s][q]
    __shared__ float Vs[32][64];   // [s][e]
    int z = blockIdx.z;
    int h = z >> 3, b = z & 7;
    const float* Pb = P + (size_t)z*LT*LT;
    const float* Vb = V + ((size_t)b*LT)*DM + h*DK;
    int q0 = blockIdx.x * 64;
    int tid = threadIdx.x;
    int tx = tid & 15, ty = tid >> 4;

    int prow = tid >> 3;          // 0..31
    int pcol = (tid & 7) * 4;     // 0..28
    int vrow = tid >> 4;          // 0..15
    int vcol = (tid & 15) * 4;

    float acc[4][4] = {};
    for (int st = 0; st < LT; st += 32) {
        float4 p0 = *(const float4*)(Pb + (size_t)(q0+prow)*LT + st + pcol);
        float4 p1 = *(const float4*)(Pb + (size_t)(q0+prow+32)*LT + st + pcol);
        float4 v0 = *(const float4*)(Vb + (size_t)(st+vrow)*DM + vcol);
        float4 v1 = *(const float4*)(Vb + (size_t)(st+vrow+16)*DM + vcol);
        __syncthreads();
        Ps[pcol+0][prow]=p0.x; Ps[pcol+1][prow]=p0.y; Ps[pcol+2][prow]=p0.z; Ps[pcol+3][prow]=p0.w;
        Ps[pcol+0][prow+32]=p1.x; Ps[pcol+1][prow+32]=p1.y; Ps[pcol+2][prow+32]=p1.z; Ps[pcol+3][prow+32]=p1.w;
        *(float4*)&Vs[vrow][vcol] = v0;
        *(float4*)&Vs[vrow+16][vcol] = v1;
        __syncthreads();
#pragma unroll
        for (int s = 0; s < 32; s++) {
            float4 av = *(const float4*)&Ps[s][ty*4];
            float4 bv = *(const float4*)&Vs[s][tx*4];
            float aa[4] = {av.x,av.y,av.z,av.w};
            float bb[4] = {bv.x,bv.y,bv.z,bv.w};
#pragma unroll
            for (int i = 0; i < 4; i++)
#pragma unroll
                for (int j = 0; j < 4; j++)
                    acc[i][j] += aa[i]*bb[j];
        }
    }
#pragma unroll
    for (int i = 0; i < 4; i++) {
        float4 cv = make_float4(acc[i][0], acc[i][1], acc[i][2], acc[i][3]);
        *(float4*)(Cout + (size_t)(b*LT + q0 + ty*4 + i)*DM + h*DK + tx*4) = cv;
    }
}

// ---------------- LayerNorm over last dim (512), grid TOK, 128 threads ----------------
__global__ void ln_kernel(const float* __restrict__ in, const float* __restrict__ g,
                          const float* __restrict__ bb, float* __restrict__ out)
{
    __shared__ float sh[4];
    int row = blockIdx.x;
    int tid = threadIdx.x;
    const float* r = in + (size_t)row*DM;
    float v[4];
    float s = 0.f;
#pragma unroll
    for (int i = 0; i < 4; i++) { v[i] = r[tid + i*128]; s += v[i]; }
#pragma unroll
    for (int o = 16; o > 0; o >>= 1) s += __shfl_xor_sync(0xffffffffu, s, o);
    if ((tid & 31) == 0) sh[tid >> 5] = s;
    __syncthreads();
    s = sh[0] + sh[1] + sh[2] + sh[3];
    float mu = s * (1.f / DM);
    float s2 = 0.f;
#pragma unroll
    for (int i = 0; i < 4; i++) { float d = v[i] - mu; s2 += d*d; }
#pragma unroll
    for (int o = 16; o > 0; o >>= 1) s2 += __shfl_xor_sync(0xffffffffu, s2, o);
    __syncthreads();
    if ((tid & 31) == 0) sh[tid >> 5] = s2;
    __syncthreads();
    s2 = sh[0] + sh[1] + sh[2] + sh[3];
    float inv = rsqrtf(s2 * (1.f / DM) + EPSLN);
#pragma unroll
    for (int i = 0; i < 4; i++) {
        int d = tid + i*128;
        out[(size_t)row*DM + d] = (v[i] - mu) * inv * g[d] + bb[d];
    }
}

// ---------------- host orchestration ----------------
extern "C" void kernel_launch(void* const* d_in, const int* in_sizes, int n_in,
                              void* d_out, int out_size)
{
    (void)in_sizes; (void)n_in; (void)out_size;
    const int*   tgt_seq = (const int*)  d_in[0];
    const int*   tgt_pos = (const int*)  d_in[1];
    const int*   src_seq = (const int*)  d_in[2];
    const float* enc_out = (const float*)d_in[3];
    const float* tgt_emb = (const float*)d_in[4];
    const float* pos_emb = (const float*)d_in[5];
    const float* slf_wq  = (const float*)d_in[6];
    const float* slf_wk  = (const float*)d_in[7];
    const float* slf_wv  = (const float*)d_in[8];
    const float* slf_pw  = (const float*)d_in[9];
    const float* slf_pb  = (const float*)d_in[10];
    const float* slf_g   = (const float*)d_in[11];
    const float* slf_b   = (const float*)d_in[12];
    const float* enc_wq  = (const float*)d_in[13];
    const float* enc_wk  = (const float*)d_in[14];
    const float* enc_wv  = (const float*)d_in[15];
    const float* enc_pw  = (const float*)d_in[16];
    const float* enc_pb  = (const float*)d_in[17];
    const float* enc_g   = (const float*)d_in[18];
    const float* enc_b   = (const float*)d_in[19];
    const float* ffn_w1  = (const float*)d_in[20];
    const float* ffn_b1  = (const float*)d_in[21];
    const float* ffn_w2  = (const float*)d_in[22];
    const float* ffn_b2  = (const float*)d_in[23];
    const float* ffn_g   = (const float*)d_in[24];
    const float* ffn_b   = (const float*)d_in[25];
    float* out = (float*)d_out;

    float *x, *tmp, *q, *k, *v, *ao, *ffnb, *wT;
    cudaGetSymbolAddress((void**)&x,    g_x);
    cudaGetSymbolAddress((void**)&tmp,  g_tmp);
    cudaGetSymbolAddress((void**)&q,    g_q);
    cudaGetSymbolAddress((void**)&k,    g_k);
    cudaGetSymbolAddress((void**)&v,    g_v);
    cudaGetSymbolAddress((void**)&ao,   g_ao);
    cudaGetSymbolAddress((void**)&ffnb, g_ffn);
    cudaGetSymbolAddress((void**)&wT,   g_wT);

    // transpose qkv weights: slots 0..5 = slf q/k/v, enc q/k/v
    int wblocks = (NL*NH*DM*DK) / 256;
    transw_kernel<<<wblocks, 256>>>(slf_wq, wT + 0*WSTR);
    transw_kernel<<<wblocks, 256>>>(slf_wk, wT + 1*WSTR);
    transw_kernel<<<wblocks, 256>>>(slf_wv, wT + 2*WSTR);
    transw_kernel<<<wblocks, 256>>>(enc_wq, wT + 3*WSTR);
    transw_kernel<<<wblocks, 256>>>(enc_wk, wT + 4*WSTR);
    transw_kernel<<<wblocks, 256>>>(enc_wv, wT + 5*WSTR);

    embed_kernel<<<(TOK*DM)/256, 256>>>(tgt_seq, tgt_pos, tgt_emb, pos_emb, x);

    dim3 gProj(TOK/64, DM/64);        // 64 x 8
    dim3 gFfn1(TOK/64, DI/64);        // 64 x 32
    dim3 gScore(LT/64, LT/64, HB);    // 8 x 8 x 64
    dim3 gSoft(LT, HB);
    dim3 gPV(LT/64, 1, HB);

    for (int l = 0; l < NL; l++) {
        size_t lw = (size_t)l * DM * (NH*DK);     // per-layer offset in transposed qkv weights
        size_t lp = (size_t)l * (NH*DV) * DM;     // proj weight offset
        size_t ld = (size_t)l * DM;               // bias/gain offset

        // ---- self attention ----
        gemm_kernel<false,false,false><<<gProj,256>>>(x, wT + 0*WSTR + lw, nullptr, nullptr, q, TOK, DM, DM);
        gemm_kernel<false,false,false><<<gProj,256>>>(x, wT + 1*WSTR + lw, nullptr, nullptr, k, TOK, DM, DM);
        gemm_kernel<false,false,false><<<gProj,256>>>(x, wT + 2*WSTR + lw, nullptr, nullptr, v, TOK, DM, DM);
        float* slfA = out + X_SIZE + (size_t)l * ATT_L;
        attn_score_kernel<<<gScore,256>>>(q, k, slfA);
        softmax_kernel<true><<<gSoft,128>>>(slfA, tgt_seq);
        attn_pv_kernel<<<gPV,256>>>(slfA, v, ao);
        gemm_kernel<true,true,false><<<gProj,256>>>(ao, slf_pw + lp, slf_pb + ld, x, tmp, TOK, DM, DM);
        ln_kernel<<<TOK,128>>>(tmp, slf_g + ld, slf_b + ld, x);

        // ---- cross attention ----
        gemm_kernel<false,false,false><<<gProj,256>>>(x,       wT + 3*WSTR + lw, nullptr, nullptr, q, TOK, DM, DM);
        gemm_kernel<false,false,false><<<gProj,256>>>(enc_out, wT + 4*WSTR + lw, nullptr, nullptr, k, TOK, DM, DM);
        gemm_kernel<false,false,false><<<gProj,256>>>(enc_out, wT + 5*WSTR + lw, nullptr, nullptr, v, TOK, DM, DM);
        float* encA = out + X_SIZE + SLF_SIZE + (size_t)l * ATT_L;
        attn_score_kernel<<<gScore,256>>>(q, k, encA);
        softmax_kernel<false><<<gSoft,128>>>(encA, src_seq);
        attn_pv_kernel<<<gPV,256>>>(encA, v, ao);
        gemm_kernel<true,true,false><<<gProj,256>>>(ao, enc_pw + lp, enc_pb + ld, x, tmp, TOK, DM, DM);
        ln_kernel<<<TOK,128>>>(tmp, enc_g + ld, enc_b + ld, x);

        // ---- FFN ----
        gemm_kernel<true,false,true><<<gFfn1,256>>>(x, ffn_w1 + (size_t)l*DM*DI, ffn_b1 + (size_t)l*DI,
                                                    nullptr, ffnb, TOK, DI, DM);
        gemm_kernel<true,true,false><<<gProj,256>>>(ffnb, ffn_w2 + (size_t)l*DI*DM, ffn_b2 + ld,
                                                    x, tmp, TOK, DM, DI);
        ln_kernel<<<TOK,128>>>(tmp, ffn_g + ld, ffn_b + ld, x);
    }

    cudaMemcpyAsync(out, x, X_SIZE * sizeof(float), cudaMemcpyDeviceToDevice);
}

// round 4
// speedup vs baseline: 2.5694x; 2.5694x over previous
#include <cuda_runtime.h>
#include <cuda_bf16.h>
#include <math.h>

// ---------------- problem constants ----------------
#define TB   8
#define LT   512
#define LS   512
#define DM   512
#define NH   8
#define DK   64
#define DV   64
#define DI   2048
#define NL   6
#define TOK  (TB*LT)   // 4096
#define HB   (NH*TB)   // 64

#define EPSLN 1e-5f
#define ATT_SCALE 0.044194173824159216f   // 1/sqrt(512)

#define X_SIZE   ((size_t)TOK*DM)
#define ATT_L    ((size_t)HB*LT*LT)
#define SLF_SIZE ((size_t)NL*ATT_L)

// head-major plane stride for q/k/v/ao: [H][TOK][64], batch z=h*8+b offset = z*32768
#define HM_Z     ((size_t)LT*DK)          // 32768
#define HM_PLANE (TOK*64)                 // 262144 (plane stride for h)

// ---------------- scratch ----------------
__device__ float g_x  [TOK*DM];
__device__ float g_tmp[TOK*DM];
__device__ float g_q  [TOK*DM];   // head-major
__device__ float g_k  [TOK*DM];   // head-major
__device__ float g_v  [TOK*DM];   // head-major
__device__ float g_ao [TOK*DM];   // head-major
__device__ float g_ffn[TOK*DI];
#define WSTR ((size_t)NL*DM*NH*DK)
__device__ float g_wT[6*NL*DM*NH*DK];

// ---------------- helpers ----------------
// pack two consecutive-k floats into bf16x2 hi-plane and lo-plane (2-term split)
__device__ __forceinline__ void split2(float e, float o, unsigned &h, unsigned &l)
{
    asm("cvt.rn.satfinite.bf16x2.f32 %0, %1, %2;" : "=r"(h) : "f"(o), "f"(e));
    float eh = __uint_as_float(h << 16);
    float oh = __uint_as_float(h & 0xffff0000u);
    asm("cvt.rn.satfinite.bf16x2.f32 %0, %1, %2;" : "=r"(l) : "f"(o - oh), "f"(e - eh));
}

__device__ __forceinline__ void mma_bf16(float* d, const unsigned* a, unsigned b0, unsigned b1)
{
    asm volatile("mma.sync.aligned.m16n8k16.row.col.f32.bf16.bf16.f32 "
        "{%0,%1,%2,%3}, {%4,%5,%6,%7}, {%8,%9}, {%0,%1,%2,%3};\n"
        : "+f"(d[0]), "+f"(d[1]), "+f"(d[2]), "+f"(d[3])
        : "r"(a[0]), "r"(a[1]), "r"(a[2]), "r"(a[3]), "r"(b0), "r"(b1));
}

// ---------------- embedding ----------------
__global__ void embed_kernel(const int* __restrict__ seq, const int* __restrict__ pos,
                             const float* __restrict__ emb, const float* __restrict__ pemb,
                             float* __restrict__ x)
{
    int i = blockIdx.x * 256 + threadIdx.x;
    int t = i / DM, d = i % DM;
    x[i] = emb[(size_t)seq[t]*DM + d] + pemb[(size_t)pos[t]*DM + d];
}

// ---------------- qkv weight transpose: [NL,NH,DM,DK] -> [NL,DM,NH*DK] ----------------
__global__ void transw_kernel(const float* __restrict__ w, float* __restrict__ wt)
{
    int i = blockIdx.x * 256 + threadIdx.x;
    int e = i % DK;
    int d = (i / DK) % DM;
    int h = (i / (DK*DM)) % NH;
    int l = i / (DK*DM*NH);
    wt[((size_t)l*DM + d)*(NH*DK) + h*DK + e] = w[i];
}

// ---------------- generic bf16x3 mma GEMM ----------------
// C[M,N] = A[M,K] @ B[K,N]; BM=128, BN in {64,128}, BK=32; 256 thr; 8 warps 4x2.
// AHEAD: A is head-major [K/64][M][64] with plane stride lda.
// CHEAD: C written head-major [n>>6][M][64] with plane stride HM_PLANE.
template<int BN, bool BIAS, bool RES, bool RELU, bool AHEAD, bool CHEAD>
__global__ void __launch_bounds__(256) mm_kernel(
    const float* __restrict__ A, const float* __restrict__ B,
    const float* __restrict__ bias, const float* __restrict__ res,
    float* __restrict__ C, int K, int lda, int ldb, int ldc,
    size_t sA, size_t sB, size_t sC)
{
    constexpr int NI  = BN / 16;
    constexpr int NBI = BN / 64;          // B fill iterations
    constexpr int SBW = BN + 8;           // B smem uint row stride (mod 32 == 8)
    constexpr int ASZ = 128 * 20;         // A smem uints per buffer per plane
    constexpr int BSZ = 16 * SBW;

    extern __shared__ unsigned sm[];
    unsigned* Ah = sm;
    unsigned* Al = Ah + 2*ASZ;
    unsigned* Bh = Al + 2*ASZ;
    unsigned* Bl = Bh + 2*BSZ;

    const int tid  = threadIdx.x;
    const int lane = tid & 31, wid = tid >> 5;
    const int g  = lane >> 2, tg = lane & 3;
    const int wm = (wid & 3) * 32;
    const int wn = (wid >> 2) * (BN / 2);
    const int bm = blockIdx.x * 128;
    const int bn = blockIdx.y * BN;
    const int z  = blockIdx.z;

    const float* Ab = A + (size_t)z * sA;
    const float* Bb = B + (size_t)z * sB;
    float*       Cb = C + (size_t)z * sC;

    const int KT = K >> 5;

    float4 pa[2][2];
    float4 pb[NBI][2];

    auto loadAB = [&](int kt) {
#pragma unroll
        for (int i = 0; i < 2; i++) {
            int u4 = tid + 256*i;
            int m = u4 >> 2, c4 = (u4 & 3) * 4;
            const float* p;
            if (AHEAD)
                p = Ab + (size_t)(kt >> 1) * lda + (size_t)(bm + m) * 64 + ((kt & 1) * 32 + c4 * 2);
            else
                p = Ab + (size_t)(bm + m) * lda + kt * 32 + c4 * 2;
            pa[i][0] = *(const float4*)p;
            pa[i][1] = *(const float4*)(p + 4);
        }
#pragma unroll
        for (int i = 0; i < NBI; i++) {
            int u4 = tid + 256*i;
            int kp = u4 / (BN/4);
            int n4 = (u4 % (BN/4)) * 4;
            const float* p = Bb + (size_t)(kt*32 + 2*kp) * ldb + bn + n4;
            pb[i][0] = *(const float4*)p;
            pb[i][1] = *(const float4*)(p + ldb);
        }
    };

    auto storeAB = [&](int bsel) {
#pragma unroll
        for (int i = 0; i < 2; i++) {
            int u4 = tid + 256*i;
            int m = u4 >> 2, c4 = (u4 & 3) * 4;
            unsigned h0,h1,h2,h3,l0,l1,l2,l3;
            split2(pa[i][0].x, pa[i][0].y, h0, l0);
            split2(pa[i][0].z, pa[i][0].w, h1, l1);
            split2(pa[i][1].x, pa[i][1].y, h2, l2);
            split2(pa[i][1].z, pa[i][1].w, h3, l3);
            *(uint4*)&Ah[bsel*ASZ + m*20 + c4] = make_uint4(h0,h1,h2,h3);
            *(uint4*)&Al[bsel*ASZ + m*20 + c4] = make_uint4(l0,l1,l2,l3);
        }
#pragma unroll
        for (int i = 0; i < NBI; i++) {
            int u4 = tid + 256*i;
            int kp = u4 / (BN/4);
            int n4 = (u4 % (BN/4)) * 4;
            unsigned h0,h1,h2,h3,l0,l1,l2,l3;
            split2(pb[i][0].x, pb[i][1].x, h0, l0);
            split2(pb[i][0].y, pb[i][1].y, h1, l1);
            split2(pb[i][0].z, pb[i][1].z, h2, l2);
            split2(pb[i][0].w, pb[i][1].w, h3, l3);
            *(uint4*)&Bh[bsel*BSZ + kp*SBW + n4] = make_uint4(h0,h1,h2,h3);
            *(uint4*)&Bl[bsel*BSZ + kp*SBW + n4] = make_uint4(l0,l1,l2,l3);
        }
    };

    float acc[2][NI][4] = {};

    loadAB(0);
    storeAB(0);
    __syncthreads();

    for (int kt = 0; kt < KT; kt++) {
        int buf = kt & 1;
        if (kt + 1 < KT) loadAB(kt + 1);

        const unsigned* AhB = Ah + buf*ASZ;
        const unsigned* AlB = Al + buf*ASZ;
        const unsigned* BhB = Bh + buf*BSZ;
        const unsigned* BlB = Bl + buf*BSZ;
#pragma unroll
        for (int ks = 0; ks < 2; ks++) {
            int k0 = ks * 8;
            unsigned ah[2][4], al[2][4];
#pragma unroll
            for (int mi = 0; mi < 2; mi++) {
                int m0 = wm + mi*16;
                ah[mi][0] = AhB[(m0+g)  *20 + k0+tg];
                ah[mi][1] = AhB[(m0+g+8)*20 + k0+tg];
                ah[mi][2] = AhB[(m0+g)  *20 + k0+tg+4];
                ah[mi][3] = AhB[(m0+g+8)*20 + k0+tg+4];
                al[mi][0] = AlB[(m0+g)  *20 + k0+tg];
                al[mi][1] = AlB[(m0+g+8)*20 + k0+tg];
                al[mi][2] = AlB[(m0+g)  *20 + k0+tg+4];
                al[mi][3] = AlB[(m0+g+8)*20 + k0+tg+4];
            }
#pragma unroll
            for (int ni = 0; ni < NI; ni++) {
                int n0 = wn + ni*8 + g;
                unsigned bh0 = BhB[(k0+tg)  *SBW + n0];
                unsigned bh1 = BhB[(k0+tg+4)*SBW + n0];
                unsigned bl0 = BlB[(k0+tg)  *SBW + n0];
                unsigned bl1 = BlB[(k0+tg+4)*SBW + n0];
#pragma unroll
                for (int mi = 0; mi < 2; mi++) {
                    mma_bf16(acc[mi][ni], ah[mi], bh0, bh1);
                    mma_bf16(acc[mi][ni], ah[mi], bl0, bl1);
                    mma_bf16(acc[mi][ni], al[mi], bh0, bh1);
                }
            }
        }

        if (kt + 1 < KT) storeAB((kt + 1) & 1);
        __syncthreads();
    }

    // epilogue
#pragma unroll
    for (int mi = 0; mi < 2; mi++) {
        int r0 = bm + wm + mi*16 + g;
#pragma unroll
        for (int ni = 0; ni < NI; ni++) {
            int c = bn + wn + ni*8 + 2*tg;
            float2 v0 = make_float2(acc[mi][ni][0], acc[mi][ni][1]);
            float2 v1 = make_float2(acc[mi][ni][2], acc[mi][ni][3]);
            if (BIAS) {
                float2 bv = *(const float2*)(bias + c);
                v0.x += bv.x; v0.y += bv.y; v1.x += bv.x; v1.y += bv.y;
            }
            if (RES) {
                float2 r0v = *(const float2*)(res + (size_t)r0*ldc + c);
                float2 r1v = *(const float2*)(res + (size_t)(r0+8)*ldc + c);
                v0.x += r0v.x; v0.y += r0v.y; v1.x += r1v.x; v1.y += r1v.y;
            }
            if (RELU) {
                v0.x = fmaxf(v0.x, 0.f); v0.y = fmaxf(v0.y, 0.f);
                v1.x = fmaxf(v1.x, 0.f); v1.y = fmaxf(v1.y, 0.f);
            }
            if (CHEAD) {
                int h = c >> 6, e = c & 63;
                float* cp = Cb + (size_t)h * HM_PLANE + (size_t)r0 * 64 + e;
                *(float2*)cp = v0;
                *(float2*)(cp + 8*64) = v1;
            } else {
                float* cp = Cb + (size_t)r0 * ldc + c;
                *(float2*)cp = v0;
                *(float2*)(cp + (size_t)8*ldc) = v1;
            }
        }
    }
}

// ---------------- batched attention scores (bf16x3 mma): S = scale * Q K^T ----------------
// Q,K head-major [z][512][64]. grid (4,4,HB), 256 thr, 128x128 tile, K=64 single pass.
__global__ void __launch_bounds__(256) score_kernel(
    const float* __restrict__ Q, const float* __restrict__ Kk, float* __restrict__ out)
{
    extern __shared__ unsigned sm[];
    unsigned* Qh = sm;                 // [128][36]
    unsigned* Ql = Qh + 128*36;
    unsigned* Kh = Ql + 128*36;
    unsigned* Kl = Kh + 128*36;

    const int tid = threadIdx.x, lane = tid & 31, wid = tid >> 5;
    const int g = lane >> 2, tg = lane & 3;
    const int wm = (wid & 3) * 32, wn = (wid >> 2) * 64;
    const int q0 = blockIdx.x * 128, s0 = blockIdx.y * 128;
    const int z = blockIdx.z;

    const float* Qb = Q  + (size_t)z * HM_Z + (size_t)q0 * DK;
    const float* Kb = Kk + (size_t)z * HM_Z + (size_t)s0 * DK;

#pragma unroll
    for (int i = 0; i < 4; i++) {
        int u4 = tid + 256*i;
        int r = u4 >> 3, cu = (u4 & 7) * 4;
        const float* pq = Qb + (size_t)r * DK + cu*2;
        const float* pk = Kb + (size_t)r * DK + cu*2;
        float4 a0 = *(const float4*)pq;
        float4 a1 = *(const float4*)(pq + 4);
        float4 b0 = *(const float4*)pk;
        float4 b1 = *(const float4*)(pk + 4);
        unsigned h0,h1,h2,h3,l0,l1,l2,l3;
        split2(a0.x,a0.y,h0,l0); split2(a0.z,a0.w,h1,l1);
        split2(a1.x,a1.y,h2,l2); split2(a1.z,a1.w,h3,l3);
        *(uint4*)&Qh[r*36+cu] = make_uint4(h0,h1,h2,h3);
        *(uint4*)&Ql[r*36+cu] = make_uint4(l0,l1,l2,l3);
        split2(b0.x,b0.y,h0,l0); split2(b0.z,b0.w,h1,l1);
        split2(b1.x,b1.y,h2,l2); split2(b1.z,b1.w,h3,l3);
        *(uint4*)&Kh[r*36+cu] = make_uint4(h0,h1,h2,h3);
        *(uint4*)&Kl[r*36+cu] = make_uint4(l0,l1,l2,l3);
    }
    __syncthreads();

    float acc[2][8][4] = {};
#pragma unroll
    for (int ks = 0; ks < 4; ks++) {
        int k0 = ks * 8;
        unsigned ah[2][4], al[2][4];
#pragma unroll
        for (int mi = 0; mi < 2; mi++) {
            int m0 = wm + mi*16;
            ah[mi][0] = Qh[(m0+g)  *36 + k0+tg];
            ah[mi][1] = Qh[(m0+g+8)*36 + k0+tg];
            ah[mi][2] = Qh[(m0+g)  *36 + k0+tg+4];
            ah[mi][3] = Qh[(m0+g+8)*36 + k0+tg+4];
            al[mi][0] = Ql[(m0+g)  *36 + k0+tg];
            al[mi][1] = Ql[(m0+g+8)*36 + k0+tg];
            al[mi][2] = Ql[(m0+g)  *36 + k0+tg+4];
            al[mi][3] = Ql[(m0+g+8)*36 + k0+tg+4];
        }
#pragma unroll
        for (int ni = 0; ni < 8; ni++) {
            int n0 = wn + ni*8 + g;
            unsigned bh0 = Kh[n0*36 + k0+tg];
            unsigned bh1 = Kh[n0*36 + k0+tg+4];
            unsigned bl0 = Kl[n0*36 + k0+tg];
            unsigned bl1 = Kl[n0*36 + k0+tg+4];
#pragma unroll
            for (int mi = 0; mi < 2; mi++) {
                mma_bf16(acc[mi][ni], ah[mi], bh0, bh1);
                mma_bf16(acc[mi][ni], ah[mi], bl0, bl1);
                mma_bf16(acc[mi][ni], al[mi], bh0, bh1);
            }
        }
    }

    float* Cb = out + (size_t)z * LT * LT;
#pragma unroll
    for (int mi = 0; mi < 2; mi++) {
        int r0 = q0 + wm + mi*16 + g;
#pragma unroll
        for (int ni = 0; ni < 8; ni++) {
            int c = s0 + wn + ni*8 + 2*tg;
            float2 v0 = make_float2(acc[mi][ni][0]*ATT_SCALE, acc[mi][ni][1]*ATT_SCALE);
            float2 v1 = make_float2(acc[mi][ni][2]*ATT_SCALE, acc[mi][ni][3]*ATT_SCALE);
            *(float2*)(Cb + (size_t)r0*LT + c)     = v0;
            *(float2*)(Cb + (size_t)(r0+8)*LT + c) = v1;
        }
    }
}

// ---------------- masked softmax (rows of 512, in place) ----------------
template<bool SELF>
__global__ void softmax_kernel(float* __restrict__ attn, const int* __restrict__ seq)
{
    __shared__ float sh[4];
    int q = blockIdx.x;
    int z = blockIdx.y;
    int b = z & 7;
    float* row = attn + ((size_t)z*LT + q)*LT;
    int tid = threadIdx.x;
    float v[4];
    float mx = -INFINITY;
#pragma unroll
    for (int i = 0; i < 4; i++) {
        int s = tid + i*128;
        bool m;
        if (SELF) m = (s > q) || (seq[b*LT + s] == 0);
        else      m = (seq[b*LS + s] == 0);
        float val = m ? -INFINITY : row[s];
        v[i] = val;
        mx = fmaxf(mx, val);
    }
#pragma unroll
    for (int o = 16; o > 0; o >>= 1) mx = fmaxf(mx, __shfl_xor_sync(0xffffffffu, mx, o));
    if ((tid & 31) == 0) sh[tid >> 5] = mx;
    __syncthreads();
    mx = fmaxf(fmaxf(sh[0], sh[1]), fmaxf(sh[2], sh[3]));
    float sum = 0.f;
#pragma unroll
    for (int i = 0; i < 4; i++) { v[i] = __expf(v[i] - mx); sum += v[i]; }
#pragma unroll
    for (int o = 16; o > 0; o >>= 1) sum += __shfl_xor_sync(0xffffffffu, sum, o);
    __syncthreads();
    if ((tid & 31) == 0) sh[tid >> 5] = sum;
    __syncthreads();
    sum = sh[0] + sh[1] + sh[2] + sh[3];
    float inv = 1.f / sum;
#pragma unroll
    for (int i = 0; i < 4; i++) row[tid + i*128] = v[i] * inv;
}

// ---------------- LayerNorm ----------------
__global__ void ln_kernel(const float* __restrict__ in, const float* __restrict__ g,
                          const float* __restrict__ bb, float* __restrict__ out)
{
    __shared__ float sh[4];
    int row = blockIdx.x;
    int tid = threadIdx.x;
    const float* r = in + (size_t)row*DM;
    float v[4];
    float s = 0.f;
#pragma unroll
    for (int i = 0; i < 4; i++) { v[i] = r[tid + i*128]; s += v[i]; }
#pragma unroll
    for (int o = 16; o > 0; o >>= 1) s += __shfl_xor_sync(0xffffffffu, s, o);
    if ((tid & 31) == 0) sh[tid >> 5] = s;
    __syncthreads();
    s = sh[0] + sh[1] + sh[2] + sh[3];
    float mu = s * (1.f / DM);
    float s2 = 0.f;
#pragma unroll
    for (int i = 0; i < 4; i++) { float d = v[i] - mu; s2 += d*d; }
#pragma unroll
    for (int o = 16; o > 0; o >>= 1) s2 += __shfl_xor_sync(0xffffffffu, s2, o);
    __syncthreads();
    if ((tid & 31) == 0) sh[tid >> 5] = s2;
    __syncthreads();
    s2 = sh[0] + sh[1] + sh[2] + sh[3];
    float inv = rsqrtf(s2 * (1.f / DM) + EPSLN);
#pragma unroll
    for (int i = 0; i < 4; i++) {
        int d = tid + i*128;
        out[(size_t)row*DM + d] = (v[i] - mu) * inv * g[d] + bb[d];
    }
}

// ---------------- host orchestration ----------------
extern "C" void kernel_launch(void* const* d_in, const int* in_sizes, int n_in,
                              void* d_out, int out_size)
{
    (void)in_sizes; (void)n_in; (void)out_size;
    const int*   tgt_seq = (const int*)  d_in[0];
    const int*   tgt_pos = (const int*)  d_in[1];
    const int*   src_seq = (const int*)  d_in[2];
    const float* enc_out = (const float*)d_in[3];
    const float* tgt_emb = (const float*)d_in[4];
    const float* pos_emb = (const float*)d_in[5];
    const float* slf_wq  = (const float*)d_in[6];
    const float* slf_wk  = (const float*)d_in[7];
    const float* slf_wv  = (const float*)d_in[8];
    const float* slf_pw  = (const float*)d_in[9];
    const float* slf_pb  = (const float*)d_in[10];
    const float* slf_g   = (const float*)d_in[11];
    const float* slf_b   = (const float*)d_in[12];
    const float* enc_wq  = (const float*)d_in[13];
    const float* enc_wk  = (const float*)d_in[14];
    const float* enc_wv  = (const float*)d_in[15];
    const float* enc_pw  = (const float*)d_in[16];
    const float* enc_pb  = (const float*)d_in[17];
    const float* enc_g   = (const float*)d_in[18];
    const float* enc_b   = (const float*)d_in[19];
    const float* ffn_w1  = (const float*)d_in[20];
    const float* ffn_b1  = (const float*)d_in[21];
    const float* ffn_w2  = (const float*)d_in[22];
    const float* ffn_b2  = (const float*)d_in[23];
    const float* ffn_g   = (const float*)d_in[24];
    const float* ffn_b   = (const float*)d_in[25];
    float* out = (float*)d_out;

    float *x, *tmp, *q, *k, *v, *ao, *ffnb, *wT;
    cudaGetSymbolAddress((void**)&x,    g_x);
    cudaGetSymbolAddress((void**)&tmp,  g_tmp);
    cudaGetSymbolAddress((void**)&q,    g_q);
    cudaGetSymbolAddress((void**)&k,    g_k);
    cudaGetSymbolAddress((void**)&v,    g_v);
    cudaGetSymbolAddress((void**)&ao,   g_ao);
    cudaGetSymbolAddress((void**)&ffnb, g_ffn);
    cudaGetSymbolAddress((void**)&wT,   g_wT);

    // kernel instantiations
    auto kProj  = mm_kernel<128,false,false,false,false,true >;  // qkv proj -> head-major
    auto kOutP  = mm_kernel<128,true, true, false,true, false>;  // out proj (A head-major)
    auto kFfn1  = mm_kernel<128,true, false,true, false,false>;
    auto kFfn2  = mm_kernel<128,true, true, false,false,false>;
    auto kPV    = mm_kernel<64, false,false,false,false,false>;

    const int SMEM128 = (2*2*128*20 + 2*2*16*136) * 4;  // 75776
    const int SMEM64  = (2*2*128*20 + 2*2*16*72)  * 4;  // 59392
    const int SMEMSC  = (4*128*36) * 4;                 // 73728
    cudaFuncSetAttribute(kProj, cudaFuncAttributeMaxDynamicSharedMemorySize, SMEM128);
    cudaFuncSetAttribute(kOutP, cudaFuncAttributeMaxDynamicSharedMemorySize, SMEM128);
    cudaFuncSetAttribute(kFfn1, cudaFuncAttributeMaxDynamicSharedMemorySize, SMEM128);
    cudaFuncSetAttribute(kFfn2, cudaFuncAttributeMaxDynamicSharedMemorySize, SMEM128);
    cudaFuncSetAttribute(kPV,   cudaFuncAttributeMaxDynamicSharedMemorySize, SMEM64);
    cudaFuncSetAttribute(score_kernel, cudaFuncAttributeMaxDynamicSharedMemorySize, SMEMSC);

    // qkv weight transpose
    int wblocks = (NL*NH*DM*DK) / 256;
    transw_kernel<<<wblocks, 256>>>(slf_wq, wT + 0*WSTR);
    transw_kernel<<<wblocks, 256>>>(slf_wk, wT + 1*WSTR);
    transw_kernel<<<wblocks, 256>>>(slf_wv, wT + 2*WSTR);
    transw_kernel<<<wblocks, 256>>>(enc_wq, wT + 3*WSTR);
    transw_kernel<<<wblocks, 256>>>(enc_wk, wT + 4*WSTR);
    transw_kernel<<<wblocks, 256>>>(enc_wv, wT + 5*WSTR);

    embed_kernel<<<(TOK*DM)/256, 256>>>(tgt_seq, tgt_pos, tgt_emb, pos_emb, x);

    dim3 gProj(TOK/128, DM/128);      // (32,4)
    dim3 gFfn1(TOK/128, DI/128);      // (32,16)
    dim3 gSc(LT/128, LT/128, HB);     // (4,4,64)
    dim3 gPV(LT/128, 1, HB);          // (4,1,64)
    dim3 gSoft(LT, HB);

    for (int l = 0; l < NL; l++) {
        size_t lw = (size_t)l * DM * (NH*DK);
        size_t lp = (size_t)l * (NH*DV) * DM;
        size_t ld = (size_t)l * DM;

        // ---- self attention ----
        kProj<<<gProj,256,SMEM128>>>(x, wT + 0*WSTR + lw, nullptr, nullptr, q, DM, DM, DM, DM, 0,0,0);
        kProj<<<gProj,256,SMEM128>>>(x, wT + 1*WSTR + lw, nullptr, nullptr, k, DM, DM, DM, DM, 0,0,0);
        kProj<<<gProj,256,SMEM128>>>(x, wT + 2*WSTR + lw, nullptr, nullptr, v, DM, DM, DM, DM, 0,0,0);
        float* slfA = out + X_SIZE + (size_t)l * ATT_L;
        score_kernel<<<gSc,256,SMEMSC>>>(q, k, slfA);
        softmax_kernel<true><<<gSoft,128>>>(slfA, tgt_seq);
        kPV<<<gPV,256,SMEM64>>>(slfA, v, nullptr, nullptr, ao, LT, LT, DK, DK,
                                (size_t)LT*LT, HM_Z, HM_Z);
        kOutP<<<gProj,256,SMEM128>>>(ao, slf_pw + lp, slf_pb + ld, x, tmp,
                                     DM, HM_PLANE, DM, DM, 0,0,0);
        ln_kernel<<<TOK,128>>>(tmp, slf_g + ld, slf_b + ld, x);

        // ---- cross attention ----
        kProj<<<gProj,256,SMEM128>>>(x,       wT + 3*WSTR + lw, nullptr, nullptr, q, DM, DM, DM, DM, 0,0,0);
        kProj<<<gProj,256,SMEM128>>>(enc_out, wT + 4*WSTR + lw, nullptr, nullptr, k, DM, DM, DM, DM, 0,0,0);
        kProj<<<gProj,256,SMEM128>>>(enc_out, wT + 5*WSTR + lw, nullptr, nullptr, v, DM, DM, DM, DM, 0,0,0);
        float* encA = out + X_SIZE + SLF_SIZE + (size_t)l * ATT_L;
        score_kernel<<<gSc,256,SMEMSC>>>(q, k, encA);
        softmax_kernel<false><<<gSoft,128>>>(encA, src_seq);
        kPV<<<gPV,256,SMEM64>>>(encA, v, nullptr, nullptr, ao, LT, LT, DK, DK,
                                (size_t)LT*LT, HM_Z, HM_Z);
        kOutP<<<gProj,256,SMEM128>>>(ao, enc_pw + lp, enc_pb + ld, x, tmp,
                                     DM, HM_PLANE, DM, DM, 0,0,0);
        ln_kernel<<<TOK,128>>>(tmp, enc_g + ld, enc_b + ld, x);

        // ---- FFN ----
        kFfn1<<<gFfn1,256,SMEM128>>>(x, ffn_w1 + (size_t)l*DM*DI, ffn_b1 + (size_t)l*DI,
                                     nullptr, ffnb, DM, DM, DI, DI, 0,0,0);
        kFfn2<<<gProj,256,SMEM128>>>(ffnb, ffn_w2 + (size_t)l*DI*DM, ffn_b2 + ld,
                                     x, tmp, DI, DI, DM, DM, 0,0,0);
        ln_kernel<<<TOK,128>>>(tmp, ffn_g + ld, ffn_b + ld, x);
    }

    cudaMemcpyAsync(out, x, X_SIZE * sizeof(float), cudaMemcpyDeviceToDevice);
}

// round 8
// speedup vs baseline: 3.3205x; 1.2923x over previous
#include <cuda_runtime.h>
#include <cuda_fp16.h>
#include <cstdint>
#include <math.h>

// ---------------- problem constants ----------------
#define TB   8
#define LT   512
#define LS   512
#define DM   512
#define NH   8
#define DK   64
#define DV   64
#define DI   2048
#define NL   6
#define TOK  (TB*LT)   // 4096
#define HB   (NH*TB)   // 64

#define EPSLN 1e-5f
#define ATT_SCALE 0.044194173824159216f   // 1/sqrt(512)

#define X_SIZE   ((size_t)TOK*DM)
#define ATT_L    ((size_t)HB*LT*LT)
#define SLF_SIZE ((size_t)NL*ATT_L)

// head-major plane: [plane][tok][64]
#define HM_Z     ((size_t)LT*DK)          // 32768 (per-batch stride inside a plane)
#define HM_PLANE ((size_t)TOK*64)         // 262144

// ---------------- scratch ----------------
__device__ float g_x  [TOK*DM];
__device__ float g_tmp[TOK*DM];
__device__ float g_qkv[24*TOK*64];            // self: q planes 0-7, k 8-15, v 16-23 (cross-Q reuses 0-7)
__device__ float g_kvc[NL*16*TOK*64];         // cross K planes 0-7, V 8-15, per layer
__device__ float g_ao [8*TOK*64];             // attention output, head-major
__device__ float g_ffn[TOK*DI];

// fp16 weights, [n][k] layout (k contiguous)
__device__ __half g_wqkvS[(size_t)NL*1536*512];
__device__ __half g_wqC  [(size_t)NL*512*512];
__device__ __half g_wkvC [(size_t)NL*1024*512];
__device__ __half g_pwH  [(size_t)2*NL*512*512];
__device__ __half g_f1H  [(size_t)NL*512*2048];
__device__ __half g_f2H  [(size_t)NL*512*2048];

// ---------------- helpers ----------------
__device__ __forceinline__ uint32_t smem_u32(const void* p) {
    uint32_t a;
    asm("{ .reg .u64 t; cvta.to.shared.u64 t, %1; cvt.u32.u64 %0, t; }" : "=r"(a) : "l"(p));
    return a;
}

#define LDSM4(r, addr) \
    asm volatile("ldmatrix.sync.aligned.m8n8.x4.shared.b16 {%0,%1,%2,%3}, [%4];" \
        : "=r"((r)[0]), "=r"((r)[1]), "=r"((r)[2]), "=r"((r)[3]) : "r"(addr))

__device__ __forceinline__ void mma_f16(float* d, const unsigned* a, unsigned b0, unsigned b1)
{
    asm volatile("mma.sync.aligned.m16n8k16.row.col.f32.f16.f16.f32 "
        "{%0,%1,%2,%3}, {%4,%5,%6,%7}, {%8,%9}, {%0,%1,%2,%3};\n"
        : "+f"(d[0]), "+f"(d[1]), "+f"(d[2]), "+f"(d[3])
        : "r"(a[0]), "r"(a[1]), "r"(a[2]), "r"(a[3]), "r"(b0), "r"(b1));
}

__device__ __forceinline__ unsigned packh2(float e, float o)
{
    __half2 h = __floats2half2_rn(e, o);   // low = e (even k), high = o (odd k)
    return *(unsigned*)&h;
}

// ---------------- embedding ----------------
__global__ void embed_kernel(const int* __restrict__ seq, const int* __restrict__ pos,
                             const float* __restrict__ emb, const float* __restrict__ pemb,
                             float* __restrict__ x)
{
    int i = blockIdx.x * 256 + threadIdx.x;
    int t = i / DM, d = i % DM;
    x[i] = emb[(size_t)seq[t]*DM + d] + pemb[(size_t)pos[t]*DM + d];
}

// ---------------- transpose + fp16 convert: in[b][R][C] -> out [.. n=(h*C+c) ..][R] ----------------
__global__ void transconv2_kernel(const float* __restrict__ in, __half* __restrict__ outp,
                                  int R, int C, int nhb, size_t lplane, size_t nbase)
{
    __shared__ float t[32][33];
    int bidz = blockIdx.z;
    int l = bidz / nhb, h = bidz % nhb;
    int r0 = blockIdx.x * 32, c0 = blockIdx.y * 32;
    const float* ib = in + (size_t)bidz * R * C;
#pragma unroll
    for (int i = threadIdx.y; i < 32; i += 8)
        t[i][threadIdx.x] = ib[(size_t)(r0 + i) * C + c0 + threadIdx.x];
    __syncthreads();
    __half* ob = outp + (size_t)l * lplane + nbase;
#pragma unroll
    for (int i = threadIdx.y; i < 32; i += 8)
        ob[(size_t)(h * C + c0 + i) * R + r0 + threadIdx.x] = __float2half(t[threadIdx.x][i]);
}

// ---------------- fp16 tensor-core GEMM: C[M,N] = A[M,K] @ B ----------------
// BM=BN=128, BK=32, 256 thr, 8 warps (4x2). A fp32 (converted on the fly),
// B fp16 [n][k]. Smem [row][kpair] stride 20 uints; fragments via ldmatrix.x4.
// AHEAD: A head-major [k/64][M][64] plane-stride lda. CHEAD: C -> head-major plane n>>6.
#define AST 20
template<bool BIAS, bool RES, bool RELU, bool AHEAD, bool CHEAD>
__global__ void __launch_bounds__(256) hgemm_kernel(
    const float* __restrict__ A, const __half* __restrict__ Bw,
    const float* __restrict__ bias, const float* __restrict__ res,
    float* __restrict__ C, int K, int lda, int ldc, size_t sB, size_t sC)
{
    __shared__ unsigned As[2][128*AST];
    __shared__ unsigned Bs[2][128*AST];
    const int tid = threadIdx.x, lane = tid & 31, wid = tid >> 5;
    const int g = lane >> 2, tg = lane & 3;
    const int bm = blockIdx.x * 128, bn = blockIdx.y * 128;
    const int z = blockIdx.z;
    const __half* Bz = Bw + (size_t)z * sB;
    float* Cz = C + (size_t)z * sC;
    const int KT = K >> 5;
    const int wm = (wid & 3) * 32, wn = (wid >> 2) * 64;

    const int r = tid >> 1, pp = tid & 1;
    float4 pa[4];
    uint4 pb[2];

    auto loadAB = [&](int kt) {
        const float* asrc = AHEAD
            ? A + (size_t)(kt >> 1) * lda + (size_t)(bm + r) * 64 + (kt & 1) * 32 + pp * 16
            : A + (size_t)(bm + r) * lda + kt * 32 + pp * 16;
        pa[0] = ((const float4*)asrc)[0];
        pa[1] = ((const float4*)asrc)[1];
        pa[2] = ((const float4*)asrc)[2];
        pa[3] = ((const float4*)asrc)[3];
        const uint4* bsrc = (const uint4*)(Bz + (size_t)(bn + r) * K + kt * 32 + pp * 16);
        pb[0] = bsrc[0];
        pb[1] = bsrc[1];
    };
    auto storeAB = [&](int buf) {
        unsigned u[8];
#pragma unroll
        for (int i = 0; i < 4; i++) {
            u[2*i]   = packh2(pa[i].x, pa[i].y);
            u[2*i+1] = packh2(pa[i].z, pa[i].w);
        }
        *(uint4*)&As[buf][r*AST + pp*8]     = make_uint4(u[0], u[1], u[2], u[3]);
        *(uint4*)&As[buf][r*AST + pp*8 + 4] = make_uint4(u[4], u[5], u[6], u[7]);
        *(uint4*)&Bs[buf][r*AST + pp*8]     = pb[0];
        *(uint4*)&Bs[buf][r*AST + pp*8 + 4] = pb[1];
    };

    float acc[2][8][4] = {};

    loadAB(0); storeAB(0); __syncthreads();

    const uint32_t aBase = smem_u32(&As[0][0]);
    const uint32_t bBase = smem_u32(&Bs[0][0]);
    const int frA  = (wm + (lane & 15)) * AST + (lane >> 4) * 4;
    const int frB  = (wn + (lane & 15)) * AST + (lane >> 4) * 4;

    for (int kt = 0; kt < KT; kt++) {
        int buf = kt & 1;
        if (kt + 1 < KT) loadAB(kt + 1);
        uint32_t aT = aBase + buf * (128*AST*4);
        uint32_t bT = bBase + buf * (128*AST*4);
#pragma unroll
        for (int ks = 0; ks < 2; ks++) {
            int k0 = ks * 8;
            unsigned a0[4], a1[4], bb[8][2];
            LDSM4(a0, aT + (frA + k0) * 4);
            LDSM4(a1, aT + (frA + 16*AST + k0) * 4);
#pragma unroll
            for (int nj = 0; nj < 4; nj++) {
                unsigned t4[4];
                LDSM4(t4, bT + (frB + nj*16*AST + k0) * 4);
                bb[2*nj][0]   = t4[0]; bb[2*nj+1][0] = t4[1];
                bb[2*nj][1]   = t4[2]; bb[2*nj+1][1] = t4[3];
            }
#pragma unroll
            for (int ni = 0; ni < 8; ni++) {
                mma_f16(acc[0][ni], a0, bb[ni][0], bb[ni][1]);
                mma_f16(acc[1][ni], a1, bb[ni][0], bb[ni][1]);
            }
        }
        if (kt + 1 < KT) storeAB((kt + 1) & 1);
        __syncthreads();
    }

#pragma unroll
    for (int mi = 0; mi < 2; mi++) {
        int rr = bm + wm + mi*16 + g;
#pragma unroll
        for (int ni = 0; ni < 8; ni++) {
            int c = bn + wn + ni*8 + 2*tg;
            float2 v0 = make_float2(acc[mi][ni][0], acc[mi][ni][1]);
            float2 v1 = make_float2(acc[mi][ni][2], acc[mi][ni][3]);
            if (BIAS) {
                float2 bv = *(const float2*)(bias + c);
                v0.x += bv.x; v0.y += bv.y; v1.x += bv.x; v1.y += bv.y;
            }
            if (RES) {
                float2 r0v = *(const float2*)(res + (size_t)rr*ldc + c);
                float2 r1v = *(const float2*)(res + (size_t)(rr+8)*ldc + c);
                v0.x += r0v.x; v0.y += r0v.y; v1.x += r1v.x; v1.y += r1v.y;
            }
            if (RELU) {
                v0.x = fmaxf(v0.x, 0.f); v0.y = fmaxf(v0.y, 0.f);
                v1.x = fmaxf(v1.x, 0.f); v1.y = fmaxf(v1.y, 0.f);
            }
            if (CHEAD) {
                int plane = c >> 6, e = c & 63;
                float* cp = Cz + (size_t)plane * HM_PLANE + (size_t)rr * 64 + e;
                *(float2*)cp = v0;
                *(float2*)(cp + 8*64) = v1;
            } else {
                float* cp = Cz + (size_t)rr * ldc + c;
                *(float2*)cp = v0;
                *(float2*)(cp + (size_t)8*ldc) = v1;
            }
        }
    }
}

// ---------------- attention scores: S = scale * Q K^T (fp16 mma + ldmatrix) ----------------
// Q/K head-major fp32; grid (4,4,HB), 128x128 tile, K=64 single pass.
#define SST 36
__global__ void __launch_bounds__(256) score_kernel(
    const float* __restrict__ Qroot, const float* __restrict__ Kroot, float* __restrict__ out)
{
    __shared__ unsigned Qs[128*SST];
    __shared__ unsigned Ks[128*SST];
    const int tid = threadIdx.x, lane = tid & 31, wid = tid >> 5;
    const int g = lane >> 2, tg = lane & 3;
    const int wm = (wid & 3) * 32, wn = (wid >> 2) * 64;
    const int q0 = blockIdx.x * 128, s0 = blockIdx.y * 128;
    const int z = blockIdx.z, h = z >> 3, b = z & 7;

    const float* Qb = Qroot + (size_t)h * HM_PLANE + (size_t)b * HM_Z + (size_t)q0 * DK;
    const float* Kb = Kroot + (size_t)h * HM_PLANE + (size_t)b * HM_Z + (size_t)s0 * DK;

    {
        int r = tid >> 1, part = tid & 1;
        const float* qsrc = Qb + (size_t)r * DK + part * 32;
        const float* ksrc = Kb + (size_t)r * DK + part * 32;
        unsigned uq[16], uk[16];
#pragma unroll
        for (int i = 0; i < 8; i++) {
            float4 a = ((const float4*)qsrc)[i];
            float4 bq = ((const float4*)ksrc)[i];
            uq[2*i]   = packh2(a.x, a.y);  uq[2*i+1] = packh2(a.z, a.w);
            uk[2*i]   = packh2(bq.x, bq.y); uk[2*i+1] = packh2(bq.z, bq.w);
        }
        int o = r*SST + part*16;
#pragma unroll
        for (int i = 0; i < 4; i++) {
            *(uint4*)&Qs[o + 4*i] = make_uint4(uq[4*i], uq[4*i+1], uq[4*i+2], uq[4*i+3]);
            *(uint4*)&Ks[o + 4*i] = make_uint4(uk[4*i], uk[4*i+1], uk[4*i+2], uk[4*i+3]);
        }
    }
    __syncthreads();

    const uint32_t qB = smem_u32(&Qs[0]);
    const uint32_t kB = smem_u32(&Ks[0]);
    const int frA = (wm + (lane & 15)) * SST + (lane >> 4) * 4;
    const int frB = (wn + (lane & 15)) * SST + (lane >> 4) * 4;

    float acc[2][8][4] = {};
#pragma unroll
    for (int ks = 0; ks < 4; ks++) {
        int k0 = ks * 8;
        unsigned a0[4], a1[4], bb[8][2];
        LDSM4(a0, qB + (frA + k0) * 4);
        LDSM4(a1, qB + (frA + 16*SST + k0) * 4);
#pragma unroll
        for (int nj = 0; nj < 4; nj++) {
            unsigned t4[4];
            LDSM4(t4, kB + (frB + nj*16*SST + k0) * 4);
            bb[2*nj][0] = t4[0]; bb[2*nj+1][0] = t4[1];
            bb[2*nj][1] = t4[2]; bb[2*nj+1][1] = t4[3];
        }
#pragma unroll
        for (int ni = 0; ni < 8; ni++) {
            mma_f16(acc[0][ni], a0, bb[ni][0], bb[ni][1]);
            mma_f16(acc[1][ni], a1, bb[ni][0], bb[ni][1]);
        }
    }

    float* Cb = out + (size_t)z * LT * LT;
#pragma unroll
    for (int mi = 0; mi < 2; mi++) {
        int rr = q0 + wm + mi*16 + g;
#pragma unroll
        for (int ni = 0; ni < 8; ni++) {
            int c = s0 + wn + ni*8 + 2*tg;
            float2 v0 = make_float2(acc[mi][ni][0]*ATT_SCALE, acc[mi][ni][1]*ATT_SCALE);
            float2 v1 = make_float2(acc[mi][ni][2]*ATT_SCALE, acc[mi][ni][3]*ATT_SCALE);
            *(float2*)(Cb + (size_t)rr*LT + c)     = v0;
            *(float2*)(Cb + (size_t)(rr+8)*LT + c) = v1;
        }
    }
}

// ---------------- P @ V (fp16 mma + ldmatrix), out head-major ----------------
// grid (4,1,HB). BM=128 q, BN=64 e, BK=32 s, double-buffered.
__global__ void __launch_bounds__(256) pv_kernel(
    const float* __restrict__ P, const float* __restrict__ Vroot, float* __restrict__ ao)
{
    __shared__ unsigned As[2][128*AST];
    __shared__ unsigned Bs[2][64*AST];
    const int tid = threadIdx.x, lane = tid & 31, wid = tid >> 5;
    const int g = lane >> 2, tg = lane & 3;
    const int wm = (wid & 3) * 32, wn = (wid >> 2) * 32;
    const int bm = blockIdx.x * 128;
    const int z = blockIdx.z, h = z >> 3, b = z & 7;

    const float* Pz = P + (size_t)z * LT * LT;
    const float* Vz = Vroot + (size_t)h * HM_PLANE + (size_t)b * HM_Z;

    const int r = tid >> 1, pp = tid & 1;
    const int vn = tid >> 2, kg = (tid & 3) * 4;
    float4 pa[4];
    float pvv[8];

    auto loadAB = [&](int kt) {
        const float* asrc = Pz + (size_t)(bm + r) * LT + kt * 32 + pp * 16;
        pa[0] = ((const float4*)asrc)[0];
        pa[1] = ((const float4*)asrc)[1];
        pa[2] = ((const float4*)asrc)[2];
        pa[3] = ((const float4*)asrc)[3];
#pragma unroll
        for (int j = 0; j < 8; j++)
            pvv[j] = Vz[(size_t)(kt*32 + kg*2 + j) * 64 + vn];
    };
    auto storeAB = [&](int buf) {
        unsigned u[8];
#pragma unroll
        for (int i = 0; i < 4; i++) {
            u[2*i]   = packh2(pa[i].x, pa[i].y);
            u[2*i+1] = packh2(pa[i].z, pa[i].w);
        }
        *(uint4*)&As[buf][r*AST + pp*8]     = make_uint4(u[0], u[1], u[2], u[3]);
        *(uint4*)&As[buf][r*AST + pp*8 + 4] = make_uint4(u[4], u[5], u[6], u[7]);
        unsigned w0 = packh2(pvv[0], pvv[1]);
        unsigned w1 = packh2(pvv[2], pvv[3]);
        unsigned w2 = packh2(pvv[4], pvv[5]);
        unsigned w3 = packh2(pvv[6], pvv[7]);
        *(uint4*)&Bs[buf][vn*AST + kg] = make_uint4(w0, w1, w2, w3);
    };

    float acc[2][4][4] = {};

    loadAB(0); storeAB(0); __syncthreads();

    const uint32_t aBase = smem_u32(&As[0][0]);
    const uint32_t bBase = smem_u32(&Bs[0][0]);
    const int frA = (wm + (lane & 15)) * AST + (lane >> 4) * 4;
    const int frB = (wn + (lane & 15)) * AST + (lane >> 4) * 4;

    const int KT = LT / 32;   // 16
    for (int kt = 0; kt < KT; kt++) {
        int buf = kt & 1;
        if (kt + 1 < KT) loadAB(kt + 1);
        uint32_t aT = aBase + buf * (128*AST*4);
        uint32_t bT = bBase + buf * (64*AST*4);
#pragma unroll
        for (int ks = 0; ks < 2; ks++) {
            int k0 = ks * 8;
            unsigned a0[4], a1[4], bb[4][2];
            LDSM4(a0, aT + (frA + k0) * 4);
            LDSM4(a1, aT + (frA + 16*AST + k0) * 4);
#pragma unroll
            for (int nj = 0; nj < 2; nj++) {
                unsigned t4[4];
                LDSM4(t4, bT + (frB + nj*16*AST + k0) * 4);
                bb[2*nj][0] = t4[0]; bb[2*nj+1][0] = t4[1];
                bb[2*nj][1] = t4[2]; bb[2*nj+1][1] = t4[3];
            }
#pragma unroll
            for (int ni = 0; ni < 4; ni++) {
                mma_f16(acc[0][ni], a0, bb[ni][0], bb[ni][1]);
                mma_f16(acc[1][ni], a1, bb[ni][0], bb[ni][1]);
            }
        }
        if (kt + 1 < KT) storeAB((kt + 1) & 1);
        __syncthreads();
    }

    float* aoh = ao + (size_t)h * HM_PLANE;
#pragma unroll
    for (int mi = 0; mi < 2; mi++) {
        int rr = bm + wm + mi*16 + g;
        size_t tok = (size_t)b * LT + rr;
#pragma unroll
        for (int ni = 0; ni < 4; ni++) {
            int c = wn + ni*8 + 2*tg;
            *(float2*)(aoh + tok*64 + c)     = make_float2(acc[mi][ni][0], acc[mi][ni][1]);
            *(float2*)(aoh + (tok+8)*64 + c) = make_float2(acc[mi][ni][2], acc[mi][ni][3]);
        }
    }
}

// ---------------- masked softmax over rows of 512, in place ----------------
template<bool SELF>
__global__ void softmax_kernel(float* __restrict__ attn, const int* __restrict__ seq)
{
    __shared__ float sh[4];
    int q = blockIdx.x;
    int z = blockIdx.y;
    int b = z & 7;
    float* row = attn + ((size_t)z*LT + q)*LT;
    int tid = threadIdx.x;
    float v[4];
    float mx = -INFINITY;
#pragma unroll
    for (int i = 0; i < 4; i++) {
        int s = tid + i*128;
        bool m;
        if (SELF) m = (s > q) || (seq[b*LT + s] == 0);
        else      m = (seq[b*LS + s] == 0);
        float val = m ? -INFINITY : row[s];
        v[i] = val;
        mx = fmaxf(mx, val);
    }
#pragma unroll
    for (int o = 16; o > 0; o >>= 1) mx = fmaxf(mx, __shfl_xor_sync(0xffffffffu, mx, o));
    if ((tid & 31) == 0) sh[tid >> 5] = mx;
    __syncthreads();
    mx = fmaxf(fmaxf(sh[0], sh[1]), fmaxf(sh[2], sh[3]));
    float sum = 0.f;
#pragma unroll
    for (int i = 0; i < 4; i++) { v[i] = __expf(v[i] - mx); sum += v[i]; }
#pragma unroll
    for (int o = 16; o > 0; o >>= 1) sum += __shfl_xor_sync(0xffffffffu, sum, o);
    __syncthreads();
    if ((tid & 31) == 0) sh[tid >> 5] = sum;
    __syncthreads();
    sum = sh[0] + sh[1] + sh[2] + sh[3];
    float inv = 1.f / sum;
#pragma unroll
    for (int i = 0; i < 4; i++) row[tid + i*128] = v[i] * inv;
}

// ---------------- LayerNorm ----------------
__global__ void ln_kernel(const float* __restrict__ in, const float* __restrict__ g,
                          const float* __restrict__ bb, float* __restrict__ out)
{
    __shared__ float sh[4];
    int row = blockIdx.x;
    int tid = threadIdx.x;
    const float* r = in + (size_t)row*DM;
    float v[4];
    float s = 0.f;
#pragma unroll
    for (int i = 0; i < 4; i++) { v[i] = r[tid + i*128]; s += v[i]; }
#pragma unroll
    for (int o = 16; o > 0; o >>= 1) s += __shfl_xor_sync(0xffffffffu, s, o);
    if ((tid & 31) == 0) sh[tid >> 5] = s;
    __syncthreads();
    s = sh[0] + sh[1] + sh[2] + sh[3];
    float mu = s * (1.f / DM);
    float s2 = 0.f;
#pragma unroll
    for (int i = 0; i < 4; i++) { float d = v[i] - mu; s2 += d*d; }
#pragma unroll
    for (int o = 16; o > 0; o >>= 1) s2 += __shfl_xor_sync(0xffffffffu, s2, o);
    __syncthreads();
    if ((tid & 31) == 0) sh[tid >> 5] = s2;
    __syncthreads();
    s2 = sh[0] + sh[1] + sh[2] + sh[3];
    float inv = rsqrtf(s2 * (1.f / DM) + EPSLN);
#pragma unroll
    for (int i = 0; i < 4; i++) {
        int d = tid + i*128;
        out[(size_t)row*DM + d] = (v[i] - mu) * inv * g[d] + bb[d];
    }
}

// ---------------- host orchestration ----------------
extern "C" void kernel_launch(void* const* d_in, const int* in_sizes, int n_in,
                              void* d_out, int out_size)
{
    (void)in_sizes; (void)n_in; (void)out_size;
    const int*   tgt_seq = (const int*)  d_in[0];
    const int*   tgt_pos = (const int*)  d_in[1];
    const int*   src_seq = (const int*)  d_in[2];
    const float* enc_out = (const float*)d_in[3];
    const float* tgt_emb = (const float*)d_in[4];
    const float* pos_emb = (const float*)d_in[5];
    const float* slf_wq  = (const float*)d_in[6];
    const float* slf_wk  = (const float*)d_in[7];
    const float* slf_wv  = (const float*)d_in[8];
    const float* slf_pw  = (const float*)d_in[9];
    const float* slf_pb  = (const float*)d_in[10];
    const float* slf_g   = (const float*)d_in[11];
    const float* slf_b   = (const float*)d_in[12];
    const float* enc_wq  = (const float*)d_in[13];
    const float* enc_wk  = (const float*)d_in[14];
    const float* enc_wv  = (const float*)d_in[15];
    const float* enc_pw  = (const float*)d_in[16];
    const float* enc_pb  = (const float*)d_in[17];
    const float* enc_g   = (const float*)d_in[18];
    const float* enc_b   = (const float*)d_in[19];
    const float* ffn_w1  = (const float*)d_in[20];
    const float* ffn_b1  = (const float*)d_in[21];
    const float* ffn_w2  = (const float*)d_in[22];
    const float* ffn_b2  = (const float*)d_in[23];
    const float* ffn_g   = (const float*)d_in[24];
    const float* ffn_b   = (const float*)d_in[25];
    float* out = (float*)d_out;

    float *x, *tmp, *qkv, *kvc, *ao, *ffnb;
    __half *wqkvS, *wqC, *wkvC, *pwH, *f1H, *f2H;
    cudaGetSymbolAddress((void**)&x,     g_x);
    cudaGetSymbolAddress((void**)&tmp,   g_tmp);
    cudaGetSymbolAddress((void**)&qkv,   g_qkv);
    cudaGetSymbolAddress((void**)&kvc,   g_kvc);
    cudaGetSymbolAddress((void**)&ao,    g_ao);
    cudaGetSymbolAddress((void**)&ffnb,  g_ffn);
    cudaGetSymbolAddress((void**)&wqkvS, g_wqkvS);
    cudaGetSymbolAddress((void**)&wqC,   g_wqC);
    cudaGetSymbolAddress((void**)&wkvC,  g_wkvC);
    cudaGetSymbolAddress((void**)&pwH,   g_pwH);
    cudaGetSymbolAddress((void**)&f1H,   g_f1H);
    cudaGetSymbolAddress((void**)&f2H,   g_f2H);

    auto hProj = hgemm_kernel<false,false,false,false,true >;  // -> head-major
    auto hOut  = hgemm_kernel<true, true, false,true, false>;  // A head-major, +bias+res
    auto hF1   = hgemm_kernel<true, false,true, false,false>;  // +bias+relu
    auto hF2   = hgemm_kernel<true, true, false,false,false>;  // +bias+res

    dim3 tcb(32, 8);
    // weight prep: fp16 [n][k]
    transconv2_kernel<<<dim3(16,2,48), tcb>>>(slf_wq, wqkvS, 512, 64, 8, (size_t)1536*512, (size_t)0*512*512);
    transconv2_kernel<<<dim3(16,2,48), tcb>>>(slf_wk, wqkvS, 512, 64, 8, (size_t)1536*512, (size_t)1*512*512);
    transconv2_kernel<<<dim3(16,2,48), tcb>>>(slf_wv, wqkvS, 512, 64, 8, (size_t)1536*512, (size_t)2*512*512);
    transconv2_kernel<<<dim3(16,2,48), tcb>>>(enc_wq, wqC,   512, 64, 8, (size_t)512*512,  0);
    transconv2_kernel<<<dim3(16,2,48), tcb>>>(enc_wk, wkvC,  512, 64, 8, (size_t)1024*512, 0);
    transconv2_kernel<<<dim3(16,2,48), tcb>>>(enc_wv, wkvC,  512, 64, 8, (size_t)1024*512, (size_t)512*512);
    transconv2_kernel<<<dim3(16,16,6), tcb>>>(slf_pw, pwH,                        512, 512, 1, (size_t)512*512, 0);
    transconv2_kernel<<<dim3(16,16,6), tcb>>>(enc_pw, pwH + (size_t)NL*512*512,   512, 512, 1, (size_t)512*512, 0);
    transconv2_kernel<<<dim3(16,64,6), tcb>>>(ffn_w1, f1H, 512, 2048, 1, (size_t)512*2048, 0);
    transconv2_kernel<<<dim3(64,16,6), tcb>>>(ffn_w2, f2H, 2048, 512, 1, (size_t)512*2048, 0);

    embed_kernel<<<(TOK*DM)/256, 256>>>(tgt_seq, tgt_pos, tgt_emb, pos_emb, x);

    // all layers' cross K/V in one batched launch (depends only on enc_out)
    hProj<<<dim3(32,8,6),256>>>(enc_out, wkvC, nullptr, nullptr, kvc,
                                512, 512, 0, (size_t)1024*512, (size_t)16*HM_PLANE);

    dim3 gSc(4, 4, HB);
    dim3 gPV(4, 1, HB);
    dim3 gSoft(LT, HB);

    for (int l = 0; l < NL; l++) {
        size_t ld = (size_t)l * DM;
        const float* kvl = kvc + (size_t)l * 16 * HM_PLANE;

        // ---- self attention ----
        hProj<<<dim3(32,12),256>>>(x, wqkvS + (size_t)l*1536*512, nullptr, nullptr, qkv,
                                   512, 512, 0, 0, 0);
        float* slfA = out + X_SIZE + (size_t)l * ATT_L;
        score_kernel<<<gSc,256>>>(qkv, qkv + 8*HM_PLANE, slfA);
        softmax_kernel<true><<<gSoft,128>>>(slfA, tgt_seq);
        pv_kernel<<<gPV,256>>>(slfA, qkv + 16*HM_PLANE, ao);
        hOut<<<dim3(32,4),256>>>(ao, pwH + (size_t)l*512*512, slf_pb + ld, x, tmp,
                                 512, HM_PLANE, 512, 0, 0);
        ln_kernel<<<TOK,128>>>(tmp, slf_g + ld, slf_b + ld, x);

        // ---- cross attention ----
        hProj<<<dim3(32,4),256>>>(x, wqC + (size_t)l*512*512, nullptr, nullptr, qkv,
                                  512, 512, 0, 0, 0);
        float* encA = out + X_SIZE + SLF_SIZE + (size_t)l * ATT_L;
        score_kernel<<<gSc,256>>>(qkv, kvl, encA);
        softmax_kernel<false><<<gSoft,128>>>(encA, src_seq);
        pv_kernel<<<gPV,256>>>(encA, kvl + 8*HM_PLANE, ao);
        hOut<<<dim3(32,4),256>>>(ao, pwH + (size_t)(NL + l)*512*512, enc_pb + ld, x, tmp,
                                 512, HM_PLANE, 512, 0, 0);
        ln_kernel<<<TOK,128>>>(tmp, enc_g + ld, enc_b + ld, x);

        // ---- FFN ----
        hF1<<<dim3(32,16),256>>>(x, f1H + (size_t)l*512*2048, ffn_b1 + (size_t)l*DI, nullptr,
                                 ffnb, 512, 512, DI, 0, 0);
        hF2<<<dim3(32,4),256>>>(ffnb, f2H + (size_t)l*512*2048, ffn_b2 + ld, x, tmp,
                                2048, DI, 512, 0, 0);
        ln_kernel<<<TOK,128>>>(tmp, ffn_g + ld, ffn_b + ld, x);
    }

    cudaMemcpyAsync(out, x, X_SIZE * sizeof(float), cudaMemcpyDeviceToDevice);
}